// round 9
// baseline (speedup 1.0000x reference)
#include <cuda_runtime.h>
#include <cuda_bf16.h>

#define NUM_AA 20
#define FEAT_DIM 16
#define LUT_SIZE (NUM_AA * NUM_AA)

// ---------------------------------------------------------------------------
// Fused kernel, R3-shaped gather: exactly ONE float4 of output per thread.
// Prologue per CTA: build the 400-entry tanh LUT in shared memory via the
// factorization  delta^T M delta = (f_i M - f_j M) . (f_i - f_j).
// ---------------------------------------------------------------------------
__global__ void __launch_bounds__(256)
snack_fused(const float* __restrict__ features,
            const float* __restrict__ M,
            const int4*  __restrict__ ii4,
            const int4*  __restrict__ jj4,
            float4*      __restrict__ out4,
            int n4)
{
    __shared__ float sF [NUM_AA * FEAT_DIM];   // 320 floats
    __shared__ float sM [FEAT_DIM * FEAT_DIM]; // 256 floats
    __shared__ float sFM[NUM_AA * FEAT_DIM];   // 320 floats: F @ M
    __shared__ float s_lut[LUT_SIZE];          // 400 floats

    const int tid = threadIdx.x;

    // ---- Stage F and M ----
    if (tid < NUM_AA * FEAT_DIM) sF[tid] = features[tid];
    else if (tid < NUM_AA * FEAT_DIM + 64) {
        // spread remaining 64 threads over nothing; F rows 256..319 below
    }
    // remaining 64 F entries
    if (tid < 64) sF[256 + tid] = features[256 + tid];
    sM[tid] = M[tid];                          // blockDim == 256 == 16*16
    __syncthreads();

    // ---- FM[i][e] = sum_d F[i][d] * M[d][e]  (320 entries) ----
    for (int k = tid; k < NUM_AA * FEAT_DIM; k += 256) {
        int i = k >> 4, e = k & 15;
        float acc = 0.0f;
#pragma unroll
        for (int d = 0; d < FEAT_DIM; d++)
            acc = fmaf(sF[i * FEAT_DIM + d], sM[d * FEAT_DIM + e], acc);
        sFM[k] = acc;
    }
    __syncthreads();

    // ---- lut[i][j] = tanh( (FM_i - FM_j) . (F_i - F_j) ) ----
    for (int k = tid; k < LUT_SIZE; k += 256) {
        int i = k / NUM_AA, j = k - i * NUM_AA;
        float acc = 0.0f;
#pragma unroll
        for (int e = 0; e < FEAT_DIM; e++) {
            float dm = sFM[i * FEAT_DIM + e] - sFM[j * FEAT_DIM + e];
            float df = sF [i * FEAT_DIM + e] - sF [j * FEAT_DIM + e];
            acc = fmaf(dm, df, acc);
        }
        s_lut[k] = tanhf(acc);
    }
    __syncthreads();

    // ---- Gather: one int4/int4/float4 chunk per thread (R3 shape) ----
    int t = blockIdx.x * 256 + tid;
    if (t >= n4) return;

    int4 a = ii4[t];
    int4 b = jj4[t];

    float4 o;
    o.x = s_lut[a.x * NUM_AA + b.x];
    o.y = s_lut[a.y * NUM_AA + b.y];
    o.z = s_lut[a.z * NUM_AA + b.z];
    o.w = s_lut[a.w * NUM_AA + b.w];

    out4[t] = o;
}

// ---------------------------------------------------------------------------
// Tail: direct per-element compute (only launched if n % 4 != 0; never for
// the benchmark's n = 2^23). Cheap direct math, no LUT needed.
// ---------------------------------------------------------------------------
__global__ void snack_tail(const float* __restrict__ features,
                           const float* __restrict__ M,
                           const int* __restrict__ ii,
                           const int* __restrict__ jj,
                           float* __restrict__ out,
                           int start, int n)
{
    int t = start + blockIdx.x * blockDim.x + threadIdx.x;
    if (t >= n) return;
    int i = ii[t], j = jj[t];
    float delta[FEAT_DIM];
#pragma unroll
    for (int d = 0; d < FEAT_DIM; d++)
        delta[d] = features[i * FEAT_DIM + d] - features[j * FEAT_DIM + d];
    float dist = 0.0f;
#pragma unroll
    for (int d = 0; d < FEAT_DIM; d++) {
        float md = 0.0f;
#pragma unroll
        for (int e = 0; e < FEAT_DIM; e++)
            md = fmaf(M[d * FEAT_DIM + e], delta[e], md);
        dist = fmaf(delta[d], md, dist);
    }
    out[t] = tanhf(dist);
}

extern "C" void kernel_launch(void* const* d_in, const int* in_sizes, int n_in,
                              void* d_out, int out_size) {
    const float* features = (const float*)d_in[0];
    const float* M        = (const float*)d_in[1];
    const int*   idx_i    = (const int*)d_in[2];
    const int*   idx_j    = (const int*)d_in[3];
    float*       out      = (float*)d_out;

    int n  = in_sizes[2];
    int n4 = n / 4;

    if (n4 > 0) {
        int blocks = (n4 + 255) / 256;   // 8192 for n = 2^23
        snack_fused<<<blocks, 256>>>(features, M,
                                     (const int4*)idx_i, (const int4*)idx_j,
                                     (float4*)out, n4);
    }

    int done = n4 * 4;
    int rem  = n - done;
    if (rem > 0) {
        snack_tail<<<(rem + 255) / 256, 256>>>(features, M, idx_i, idx_j,
                                               out, done, n);
    }
}

// round 10
// speedup vs baseline: 3.4309x; 3.4309x over previous
#include <cuda_runtime.h>
#include <cuda_bf16.h>

#define NUM_AA 20
#define FEAT_DIM 16
#define LUT_SIZE (NUM_AA * NUM_AA)
#define NTRI 210                    // 20*21/2 upper-triangle entries (incl diag)
#define GRID_BLOCKS (148 * 8)

// ---------------------------------------------------------------------------
// Fused kernel: cheap symmetric LUT prologue + grid-stride float4 gather.
//   delta^T M delta = (F_i M - F_j M) . (F_i - F_j), symmetric in (i,j).
// ---------------------------------------------------------------------------
__global__ void __launch_bounds__(256, 8)
snack_fused(const float* __restrict__ features,
            const float* __restrict__ M,
            const int4*  __restrict__ ii4,
            const int4*  __restrict__ jj4,
            float4*      __restrict__ out4,
            int n4)
{
    __shared__ float sF [NUM_AA * FEAT_DIM];    // 320
    __shared__ float sM [FEAT_DIM * FEAT_DIM];  // 256
    __shared__ float sFM[NUM_AA * FEAT_DIM];    // 320
    __shared__ float s_lut[LUT_SIZE];           // 400

    const int tid = threadIdx.x;

    // ---- Stage F and M ----
    sF[tid] = features[tid];
    if (tid < 64) sF[256 + tid] = features[256 + tid];
    sM[tid] = M[tid];
    __syncthreads();

    // ---- FM = F @ M  (320 entries, 16 FMA each) ----
    for (int k = tid; k < NUM_AA * FEAT_DIM; k += 256) {
        const int i = k >> 4, e = k & 15;
        float acc = 0.0f;
#pragma unroll
        for (int d = 0; d < FEAT_DIM; d++)
            acc = fmaf(sF[i * FEAT_DIM + d], sM[d * FEAT_DIM + e], acc);
        sFM[k] = acc;
    }
    __syncthreads();

    // ---- Symmetric LUT: 210 upper-triangle entries, one per thread ----
    if (tid < NTRI) {
        // map tid -> (i, j), i <= j, row-major over the upper triangle
        int i = 0, rem = tid;
#pragma unroll
        for (int r = 0; r < NUM_AA - 1; r++) {
            if (i == r && rem >= NUM_AA - r) { rem -= NUM_AA - r; i = r + 1; }
        }
        const int j = i + rem;

        const float4* F4  = (const float4*)sF;
        const float4* FM4 = (const float4*)sFM;
        float acc = 0.0f;
#pragma unroll
        for (int q = 0; q < 4; q++) {
            float4 fi = F4 [i * 4 + q], fj = F4 [j * 4 + q];
            float4 mi = FM4[i * 4 + q], mj = FM4[j * 4 + q];
            acc = fmaf(mi.x - mj.x, fi.x - fj.x, acc);
            acc = fmaf(mi.y - mj.y, fi.y - fj.y, acc);
            acc = fmaf(mi.z - mj.z, fi.z - fj.z, acc);
            acc = fmaf(mi.w - mj.w, fi.w - fj.w, acc);
        }
        const float v = tanhf(acc);
        s_lut[i * NUM_AA + j] = v;
        s_lut[j * NUM_AA + i] = v;
    }
    __syncthreads();

    // ---- Gather: simple grid-stride, one float4 per iteration ----
    const int stride = gridDim.x * blockDim.x;
#pragma unroll 2
    for (int t = blockIdx.x * blockDim.x + tid; t < n4; t += stride) {
        const int4 a = ii4[t];
        const int4 b = jj4[t];
        float4 o;
        o.x = s_lut[a.x * NUM_AA + b.x];
        o.y = s_lut[a.y * NUM_AA + b.y];
        o.z = s_lut[a.z * NUM_AA + b.z];
        o.w = s_lut[a.w * NUM_AA + b.w];
        out4[t] = o;
    }
}

// ---------------------------------------------------------------------------
// Tail: direct per-element compute (only if n % 4 != 0; never for n = 2^23).
// ---------------------------------------------------------------------------
__global__ void snack_tail(const float* __restrict__ features,
                           const float* __restrict__ M,
                           const int* __restrict__ ii,
                           const int* __restrict__ jj,
                           float* __restrict__ out,
                           int start, int n)
{
    int t = start + blockIdx.x * blockDim.x + threadIdx.x;
    if (t >= n) return;
    int i = ii[t], j = jj[t];
    float delta[FEAT_DIM];
#pragma unroll
    for (int d = 0; d < FEAT_DIM; d++)
        delta[d] = features[i * FEAT_DIM + d] - features[j * FEAT_DIM + d];
    float dist = 0.0f;
#pragma unroll
    for (int d = 0; d < FEAT_DIM; d++) {
        float md = 0.0f;
#pragma unroll
        for (int e = 0; e < FEAT_DIM; e++)
            md = fmaf(M[d * FEAT_DIM + e], delta[e], md);
        dist = fmaf(delta[d], md, dist);
    }
    out[t] = tanhf(dist);
}

extern "C" void kernel_launch(void* const* d_in, const int* in_sizes, int n_in,
                              void* d_out, int out_size) {
    const float* features = (const float*)d_in[0];
    const float* M        = (const float*)d_in[1];
    const int*   idx_i    = (const int*)d_in[2];
    const int*   idx_j    = (const int*)d_in[3];
    float*       out      = (float*)d_out;

    int n  = in_sizes[2];
    int n4 = n / 4;

    if (n4 > 0) {
        int blocks = GRID_BLOCKS;
        int needed = (n4 + 255) / 256;
        if (blocks > needed) blocks = needed;
        snack_fused<<<blocks, 256>>>(features, M,
                                     (const int4*)idx_i, (const int4*)idx_j,
                                     (float4*)out, n4);
    }

    int done = n4 * 4;
    int rem  = n - done;
    if (rem > 0) {
        snack_tail<<<(rem + 255) / 256, 256>>>(features, M, idx_i, idx_j,
                                               out, done, n);
    }
}